// round 8
// baseline (speedup 1.0000x reference)
#include <cuda_runtime.h>
#include <math.h>

#define B      4096
#define T      70
#define NF     101
#define NFP    104           // padded K for x@W_k (mult of 8)
#define UNITS  125
#define UP     128           // padded K for h@U / h@Wf (mult of 8)
#define H3     375
#define H3P    384
#define TS     56            // T - LAG
#define GAMMA  28
#define OUT    202
#define KS     (UNITS*OUT)   // 25250
#define NW     (KS+OUT)      // 25452
#define CC     0.5413248546129181f
#define RROWS  14            // batch rows per CTA (2 CTAs per SM)
#define RTH    192
#define MXS    385           // odd row stride for MX/MI (conflict-free)
#define XS     20            // k-stride for X [k][slot] (mult of 4)
#define HS     16            // k-stride for H [u][slot] (mult of 4)
#define PADR   8             // OOB-safe prefetch pad rows

typedef unsigned long long ull;

// ---------------- padded weights in __device__ globals ------------------------
__device__ float g_Wkp[(NFP + PADR) * H3P];
__device__ float g_Up [(UP  + PADR) * H3P];
__device__ float g_b0p[H3P];
__device__ float g_b1p[H3P];
__device__ float g_Wf [(size_t)GAMMA * UP * H3P + PADR * H3P];
__device__ float g_Wfb[GAMMA * H3P];

// ---------------- helpers -----------------------------------------------------
__device__ __forceinline__ ull pk2(float lo, float hi) {
    ull r; asm("mov.b64 %0, {%1,%2};" : "=l"(r) : "f"(lo), "f"(hi)); return r;
}
__device__ __forceinline__ float2 upk(ull v) {
    float2 r; asm("mov.b64 {%0,%1}, %2;" : "=f"(r.x), "=f"(r.y) : "l"(v)); return r;
}
__device__ __forceinline__ void fma2(ull& d, ull a, ull b) {
    asm("fma.rn.f32x2 %0, %1, %2, %3;" : "=l"(d) : "l"(a), "l"(b), "l"(d));
}
__device__ __forceinline__ float sigf(float x) {
    return __fdividef(1.f, 1.f + __expf(-x));
}
__device__ __forceinline__ float tanhfast(float x) {
    float e = __expf(-2.f * x);
    return __fdividef(1.f - e, 1.f + e);
}
__device__ __forceinline__ float splus(float x) {
    return fmaxf(x, 0.f) + __logf(1.f + __expf(-fabsf(x)));
}

// ---------------- prep kernel (scalar padded weights, as in R4) ---------------
#define R1 (NFP * H3P)
#define R2 (R1 + UP * H3P)
#define R3 (R2 + H3P)
#define R4_ (R3 + H3P)
#define R5 (R4_ + GAMMA * UP * H3P)
#define R6 (R5 + GAMMA * H3P)

__global__ void prep_kernel(const float* __restrict__ W_k,
                            const float* __restrict__ U,
                            const float* __restrict__ bvec,
                            const float* __restrict__ loc,
                            const float* __restrict__ rho,
                            const float* __restrict__ ew0,
                            const float* __restrict__ ew) {
    int idx = blockIdx.x * blockDim.x + threadIdx.x;
    if (idx < R1) {
        int k = idx / H3P, j = idx - k * H3P;
        g_Wkp[idx] = (j < H3 && k < NF) ? W_k[k * H3 + j] : 0.f;
    } else if (idx < R2) {
        int i2 = idx - R1;
        int k = i2 / H3P, j = i2 - k * H3P;
        g_Up[i2] = (j < H3 && k < UNITS) ? U[k * H3 + j] : 0.f;
    } else if (idx < R3) {
        int j = idx - R2;
        g_b0p[j] = (j < H3) ? bvec[j] : 0.f;
    } else if (idx < R4_) {
        int j = idx - R3;
        g_b1p[j] = (j < H3) ? bvec[H3 + j] : 0.f;
    } else if (idx < R5) {
        int i2 = idx - R4_;
        int g = i2 / (UP * H3P);
        int rem = i2 - g * (UP * H3P);
        int k = rem / H3P, j = rem - k * H3P;
        float v = 0.f;
        if (j < OUT && k < UNITS) {
            int i = k * OUT + j;
            float e = g ? ew[(size_t)(g - 1) * NW + i] : ew0[i];
            v = fmaf(1e-5f + 0.01f * splus(CC + rho[i]), e, loc[i]);
        }
        g_Wf[i2] = v;
    } else if (idx < R6) {
        int i2 = idx - R5;
        int g = i2 / H3P, j = i2 - g * H3P;
        float v = 0.f;
        if (j < OUT) {
            int i = KS + j;
            float e = g ? ew[(size_t)(g - 1) * NW + i] : ew0[i];
            v = fmaf(1e-5f + 0.01f * splus(CC + rho[i]), e, loc[i]);
        }
        g_Wfb[i2] = v;
    }
}

// ---------------- 4-k chunk of packed FMAs (14 slots: rows 0..13) -------------
template<int SS>
__device__ __forceinline__ void chunk4(ull (&a)[14], const float* __restrict__ src,
                                       const float* wa, const float* wb) {
#pragma unroll
    for (int c = 0; c < 4; c++) {
        const float* s = src + c * SS;
        ulonglong2 q0 = *(const ulonglong2*)(s);       // slots 0..3
        ulonglong2 q1 = *(const ulonglong2*)(s + 4);   // slots 4..7
        ulonglong2 q2 = *(const ulonglong2*)(s + 8);   // slots 8..11
        ull p6 = *(const ull*)(s + 12);                // slots 12,13
        ull u0 = pk2(wa[c], wa[c]);
        ull u1 = pk2(wb[c], wb[c]);
        fma2(a[0], q0.x, u0);  fma2(a[1], q0.y, u0);
        fma2(a[2], q1.x, u0);  fma2(a[3], q1.y, u0);
        fma2(a[4], q2.x, u0);  fma2(a[5], q2.y, u0);
        fma2(a[6], p6,  u0);
        fma2(a[7],  q0.x, u1); fma2(a[8],  q0.y, u1);
        fma2(a[9],  q1.x, u1); fma2(a[10], q1.y, u1);
        fma2(a[11], q2.x, u1); fma2(a[12], q2.y, u1);
        fma2(a[13], p6,  u1);
    }
}

// ---------------- tile GEMM with ping-pong weight prefetch --------------------
// dst[slot][j] = sum_k src[k][slot] * W[k][j] + bias; KP mult of 8.
template<int KP, int SS>
__device__ __forceinline__ void gemm_step(const float* __restrict__ W,
                                          ull pb0, ull pb1,
                                          const float* __restrict__ src,
                                          float* __restrict__ dst,
                                          int j0, int j1) {
    ull a[14];
#pragma unroll
    for (int i = 0; i < 7; i++) { a[i] = pb0; a[7 + i] = pb1; }
    float wa0[4], wb0[4], wa1[4], wb1[4];
#pragma unroll
    for (int c = 0; c < 4; c++) {
        wa0[c] = W[c * H3P + j0];       wb0[c] = W[c * H3P + j1];
        wa1[c] = W[(4 + c) * H3P + j0]; wb1[c] = W[(4 + c) * H3P + j1];
    }
#pragma unroll 1
    for (int kc = 0; kc < KP; kc += 8) {
        const float* Wn = W + (size_t)(kc + 8) * H3P;
        chunk4<SS>(a, src + kc * SS, wa0, wb0);
#pragma unroll
        for (int c = 0; c < 4; c++) { wa0[c] = Wn[c * H3P + j0]; wb0[c] = Wn[c * H3P + j1]; }
        chunk4<SS>(a, src + (kc + 4) * SS, wa1, wb1);
#pragma unroll
        for (int c = 0; c < 4; c++) { wa1[c] = Wn[(4 + c) * H3P + j0]; wb1[c] = Wn[(4 + c) * H3P + j1]; }
    }
#pragma unroll
    for (int i = 0; i < 7; i++) {
        float2 v0 = upk(a[i]), v1 = upk(a[7 + i]);
        int r0 = 2 * i;
        dst[r0 * MXS + j0]       = v0.x;
        dst[(r0 + 1) * MXS + j0] = v0.y;
        dst[r0 * MXS + j1]       = v1.x;
        dst[(r0 + 1) * MXS + j1] = v1.y;
    }
}

// ---------------- main persistent recurrence (2 CTAs / SM) --------------------
#define SM_H    0
#define SM_MX   (UP * HS)                    // 2048
#define SM_MI   (SM_MX + RROWS * MXS + 6)    // + 5396
#define SM_X    (SM_MI + RROWS * MXS + 6)    // + 5396
#define SM_TOT  (SM_X + NFP * XS)            // + 2080 = 14920 floats = 59680 B

extern __shared__ float smem[];

__global__ __launch_bounds__(RTH, 2) void rec_kernel(
    const float* __restrict__ inp, const float* __restrict__ eps_s,
    float* __restrict__ out)
{
    float* sH  = smem + SM_H;
    float* sMX = smem + SM_MX;
    float* sMI = smem + SM_MI;
    float* sX  = smem + SM_X;

    int b0 = blockIdx.x * RROWS;
    int Rg = min(RROWS, B - b0);
    int tid = threadIdx.x;
    int j0 = tid;                 // 0..191
    int j1 = tid + 192;           // 192..383

    // pre-packed bias pairs (loaded once)
    ull pb0x = pk2(g_b0p[j0], g_b0p[j0]);
    ull pb1x = pk2(g_b0p[j1], g_b0p[j1]);
    ull pb0h = pk2(g_b1p[j0], g_b1p[j0]);
    ull pb1h = pk2(g_b1p[j1], g_b1p[j1]);

    for (int i = tid; i < UP * HS; i += RTH)  sH[i] = 0.f;
    for (int i = tid; i < NFP * XS; i += RTH) sX[i] = 0.f;

    float xr[8];
    // preload x(t=0)
    {
        int i = 0;
        for (int idx = tid; idx < Rg * NF; idx += RTH, i++)
            xr[i] = inp[((size_t)(b0 + idx / NF) * T + 0) * NF + (idx % NF)];
    }
    __syncthreads();
    {
        int i = 0;
        for (int idx = tid; idx < Rg * NF; idx += RTH, i++) {
            int r = idx / NF, f = idx - r * NF;
            sX[f * XS + r] = xr[i];
        }
    }
    __syncthreads();

    // ---------- phase 1: 56 warmup GRU steps ----------
    for (int t = 0; t < TS; t++) {
        if (t + 1 < TS) {
            int i = 0;
            for (int idx = tid; idx < Rg * NF; idx += RTH, i++)
                xr[i] = inp[((size_t)(b0 + idx / NF) * T + (t + 1)) * NF + (idx % NF)];
        }
        gemm_step<NFP, XS>(g_Wkp, pb0x, pb1x, sX, sMX, j0, j1);
        gemm_step<UP,  HS>(g_Up,  pb0h, pb1h, sH, sMI, j0, j1);
        __syncthreads();
        // GRU elementwise
        for (int idx = tid; idx < RROWS * UNITS; idx += RTH) {
            int u = idx / RROWS, s = idx - u * RROWS;
            if (s >= Rg) continue;
            const float* mx = sMX + s * MXS;
            const float* mi = sMI + s * MXS;
            float z  = sigf(mx[u] + mi[u]);
            float rg = sigf(mx[UNITS + u] + mi[UNITS + u]);
            float hh = tanhfast(fmaf(rg, mi[2 * UNITS + u], mx[2 * UNITS + u]));
            float ho = sH[u * HS + s];
            sH[u * HS + s] = fmaf(z, ho - hh, hh);
        }
        if (t + 1 < TS) {
            int i = 0;
            for (int idx = tid; idx < Rg * NF; idx += RTH, i++) {
                int r = idx / NF, f = idx - r * NF;
                sX[f * XS + r] = xr[i];
            }
        }
        __syncthreads();
    }

    // ---------- phase 2: 28 dense draws + 27 feedback GRU steps ----------
    for (int g = 0; g < GAMMA; g++) {
        if (g < GAMMA - 1) {
            int i = 0;
            for (int idx = tid; idx < Rg * NF; idx += RTH, i++)
                xr[i] = eps_s[((size_t)g * B + b0 + idx / NF) * NF + (idx % NF)];
        }
        // y = h @ Wf[g] + bf[g] -> sMI
        {
            const float* bf = g_Wfb + g * H3P;
            ull pbf0 = pk2(bf[j0], bf[j0]);
            ull pbf1 = pk2(bf[j1], bf[j1]);
            gemm_step<UP, HS>(g_Wf + (size_t)g * UP * H3P, pbf0, pbf1,
                              sH, sMI, j0, j1);
        }
        __syncthreads();
        // dist params -> output + feedback x
        {
            int i = 0;
            for (int idx = tid; idx < Rg * NF; idx += RTH, i++) {
                int r = idx / NF, f = idx - r * NF;
                float loc = sMI[r * MXS + f];
                float sc  = 1e-5f + 0.05f * splus(CC + sMI[r * MXS + NF + f]);
                size_t ob = ((size_t)(b0 + r) * GAMMA + g) * OUT;
                out[ob + f]      = loc;
                out[ob + NF + f] = sc;
                if (g < GAMMA - 1) sX[f * XS + r] = fmaf(sc, xr[i], loc);
            }
        }
        __syncthreads();
        if (g == GAMMA - 1) break;

        gemm_step<NFP, XS>(g_Wkp, pb0x, pb1x, sX, sMX, j0, j1);
        gemm_step<UP,  HS>(g_Up,  pb0h, pb1h, sH, sMI, j0, j1);
        __syncthreads();
        for (int idx = tid; idx < RROWS * UNITS; idx += RTH) {
            int u = idx / RROWS, s = idx - u * RROWS;
            if (s >= Rg) continue;
            const float* mx = sMX + s * MXS;
            const float* mi = sMI + s * MXS;
            float z  = sigf(mx[u] + mi[u]);
            float rg = sigf(mx[UNITS + u] + mi[UNITS + u]);
            float hh = tanhfast(fmaf(rg, mi[2 * UNITS + u], mx[2 * UNITS + u]));
            float ho = sH[u * HS + s];
            sH[u * HS + s] = fmaf(z, ho - hh, hh);
        }
        __syncthreads();
    }
}

// ---------------- launch ------------------------------------------------------
extern "C" void kernel_launch(void* const* d_in, const int* in_sizes, int n_in,
                              void* d_out, int out_size) {
    const float* inputs = (const float*)d_in[0];
    const float* W_k    = (const float*)d_in[1];
    const float* U      = (const float*)d_in[2];
    const float* b      = (const float*)d_in[3];
    const float* dv_loc = (const float*)d_in[4];
    const float* dv_rho = (const float*)d_in[5];
    const float* eps_w0 = (const float*)d_in[6];
    const float* eps_w  = (const float*)d_in[7];
    const float* eps_s  = (const float*)d_in[8];
    float* out = (float*)d_out;

    prep_kernel<<<(R6 + 255) / 256, 256>>>(W_k, U, b, dv_loc, dv_rho, eps_w0, eps_w);

    cudaFuncSetAttribute(rec_kernel, cudaFuncAttributeMaxDynamicSharedMemorySize,
                         SM_TOT * (int)sizeof(float));
    rec_kernel<<<(B + RROWS - 1) / RROWS, RTH, SM_TOT * sizeof(float)>>>(
        inputs, eps_s, out);
}

// round 9
// speedup vs baseline: 1.8205x; 1.8205x over previous
#include <cuda_runtime.h>
#include <math.h>

#define B      4096
#define T      70
#define NF     101
#define NFP    104           // padded K for x@W_k (mult of 8)
#define UNITS  125
#define UP     128           // padded K for h@U / h@Wf (mult of 16)
#define H3     375
#define H3P    384
#define TS     56            // T - LAG
#define GAMMA  28
#define OUT    202
#define KS     (UNITS*OUT)   // 25250
#define NW     (KS+OUT)      // 25452
#define CC     0.5413248546129181f
#define RROWS  28
#define RTH    384
#define MXS    385           // odd row stride for MX/MI (conflict-free)
#define XS     36            // k-stride for X [k][slot]
#define HS     32            // k-stride for H [u][slot]
#define PADR   16            // OOB-safe prefetch pad rows (16-deep prefetch)

typedef unsigned long long ull;

// ---------------- padded weights in __device__ globals ------------------------
__device__ float g_Wkp[(NFP + PADR) * H3P];
__device__ float g_Up [(UP  + PADR) * H3P];
__device__ float g_b0p[H3P];
__device__ float g_b1p[H3P];
__device__ float g_Wf [(size_t)GAMMA * UP * H3P + PADR * H3P];
__device__ float g_Wfb[GAMMA * H3P];

// ---------------- helpers -----------------------------------------------------
__device__ __forceinline__ ull pk2(float lo, float hi) {
    ull r; asm("mov.b64 %0, {%1,%2};" : "=l"(r) : "f"(lo), "f"(hi)); return r;
}
__device__ __forceinline__ float2 upk(ull v) {
    float2 r; asm("mov.b64 {%0,%1}, %2;" : "=f"(r.x), "=f"(r.y) : "l"(v)); return r;
}
__device__ __forceinline__ void fma2(ull& d, ull a, ull b) {
    asm("fma.rn.f32x2 %0, %1, %2, %3;" : "=l"(d) : "l"(a), "l"(b), "l"(d));
}
__device__ __forceinline__ float sigf(float x) {
    return __fdividef(1.f, 1.f + __expf(-x));
}
__device__ __forceinline__ float tanhfast(float x) {
    float e = __expf(-2.f * x);
    return __fdividef(1.f - e, 1.f + e);
}
__device__ __forceinline__ float splus(float x) {
    return fmaxf(x, 0.f) + __logf(1.f + __expf(-fabsf(x)));
}

// ---------------- prep kernel -------------------------------------------------
#define P1 (NFP * H3P)
#define P2 (P1 + UP * H3P)
#define P3 (P2 + H3P)
#define P4 (P3 + H3P)
#define P5 (P4 + GAMMA * UP * H3P)
#define P6 (P5 + GAMMA * H3P)

__global__ void prep_kernel(const float* __restrict__ W_k,
                            const float* __restrict__ U,
                            const float* __restrict__ bvec,
                            const float* __restrict__ loc,
                            const float* __restrict__ rho,
                            const float* __restrict__ ew0,
                            const float* __restrict__ ew) {
    int idx = blockIdx.x * blockDim.x + threadIdx.x;
    if (idx < P1) {
        int k = idx / H3P, j = idx - k * H3P;
        g_Wkp[idx] = (j < H3 && k < NF) ? W_k[k * H3 + j] : 0.f;
    } else if (idx < P2) {
        int i2 = idx - P1;
        int k = i2 / H3P, j = i2 - k * H3P;
        g_Up[i2] = (j < H3 && k < UNITS) ? U[k * H3 + j] : 0.f;
    } else if (idx < P3) {
        int j = idx - P2;
        g_b0p[j] = (j < H3) ? bvec[j] : 0.f;
    } else if (idx < P4) {
        int j = idx - P3;
        g_b1p[j] = (j < H3) ? bvec[H3 + j] : 0.f;
    } else if (idx < P5) {
        int i2 = idx - P4;
        int g = i2 / (UP * H3P);
        int rem = i2 - g * (UP * H3P);
        int k = rem / H3P, j = rem - k * H3P;
        float v = 0.f;
        if (j < OUT && k < UNITS) {
            int i = k * OUT + j;
            float e = g ? ew[(size_t)(g - 1) * NW + i] : ew0[i];
            v = fmaf(1e-5f + 0.01f * splus(CC + rho[i]), e, loc[i]);
        }
        g_Wf[i2] = v;
    } else if (idx < P6) {
        int i2 = idx - P5;
        int g = i2 / H3P, j = i2 - g * H3P;
        float v = 0.f;
        if (j < OUT) {
            int i = KS + j;
            float e = g ? ew[(size_t)(g - 1) * NW + i] : ew0[i];
            v = fmaf(1e-5f + 0.01f * splus(CC + rho[i]), e, loc[i]);
        }
        g_Wfb[i2] = v;
    }
}

// ---------------- 4-k chunk of packed FMAs (14 slots) -------------------------
// w[c] = (W[k][j2], W[k][j2+1]); a[0..6] accumulate col j2, a[7..13] col j2+1
template<int SS>
__device__ __forceinline__ void chunk4(ull (&a)[14], const float* __restrict__ src,
                                       const float2* w) {
#pragma unroll
    for (int c = 0; c < 4; c++) {
        const float* s = src + c * SS;
        ulonglong2 q0 = *(const ulonglong2*)(s);       // slots +0..3
        ulonglong2 q1 = *(const ulonglong2*)(s + 4);   // slots +4..7
        ulonglong2 q2 = *(const ulonglong2*)(s + 8);   // slots +8..11
        ull p6 = *(const ull*)(s + 12);                // slots +12,13
        ull u0 = pk2(w[c].x, w[c].x);
        ull u1 = pk2(w[c].y, w[c].y);
        fma2(a[0], q0.x, u0);  fma2(a[1], q0.y, u0);
        fma2(a[2], q1.x, u0);  fma2(a[3], q1.y, u0);
        fma2(a[4], q2.x, u0);  fma2(a[5], q2.y, u0);
        fma2(a[6], p6,  u0);
        fma2(a[7],  q0.x, u1); fma2(a[8],  q0.y, u1);
        fma2(a[9],  q1.x, u1); fma2(a[10], q1.y, u1);
        fma2(a[11], q2.x, u1); fma2(a[12], q2.y, u1);
        fma2(a[13], p6,  u1);
    }
}

// ---------------- tile GEMM: LDG.64 weights, 16-deep rotating prefetch --------
// dst[slot][j] for j in {j2, j2+1}; KP mult of 8; PADR>=16 beyond KP required.
template<int KP, int SS>
__device__ __forceinline__ void gemm_step(const float* __restrict__ W,
                                          ull pb0, ull pb1,
                                          const float* __restrict__ src,
                                          float* __restrict__ dst,
                                          int rb, int j2) {
    ull a[14];
#pragma unroll
    for (int i = 0; i < 7; i++) { a[i] = pb0; a[7 + i] = pb1; }
    const float* Wj = W + j2;
    float2 w0[4], w1[4], w2[4], w3[4];
#pragma unroll
    for (int c = 0; c < 4; c++) {
        w0[c] = *(const float2*)(Wj + c * H3P);
        w1[c] = *(const float2*)(Wj + (4 + c) * H3P);
        w2[c] = *(const float2*)(Wj + (8 + c) * H3P);
        w3[c] = *(const float2*)(Wj + (12 + c) * H3P);
    }
    constexpr int KP16 = (KP / 16) * 16;
#pragma unroll 1
    for (int kc = 0; kc < KP16; kc += 16) {
        const float* Wn = Wj + (size_t)(kc + 16) * H3P;
        chunk4<SS>(a, src + (kc + 0) * SS + rb, w0);
#pragma unroll
        for (int c = 0; c < 4; c++) w0[c] = *(const float2*)(Wn + c * H3P);
        chunk4<SS>(a, src + (kc + 4) * SS + rb, w1);
#pragma unroll
        for (int c = 0; c < 4; c++) w1[c] = *(const float2*)(Wn + (4 + c) * H3P);
        chunk4<SS>(a, src + (kc + 8) * SS + rb, w2);
#pragma unroll
        for (int c = 0; c < 4; c++) w2[c] = *(const float2*)(Wn + (8 + c) * H3P);
        chunk4<SS>(a, src + (kc + 12) * SS + rb, w3);
#pragma unroll
        for (int c = 0; c < 4; c++) w3[c] = *(const float2*)(Wn + (12 + c) * H3P);
    }
    if constexpr ((KP % 16) != 0) {   // remainder 8
        chunk4<SS>(a, src + KP16 * SS + rb, w0);
        chunk4<SS>(a, src + (KP16 + 4) * SS + rb, w1);
    }
#pragma unroll
    for (int i = 0; i < 7; i++) {
        float2 v0 = upk(a[i]), v1 = upk(a[7 + i]);
        int r0 = rb + 2 * i;
        dst[r0 * MXS + j2]           = v0.x;
        dst[(r0 + 1) * MXS + j2]     = v0.y;
        dst[r0 * MXS + j2 + 1]       = v1.x;
        dst[(r0 + 1) * MXS + j2 + 1] = v1.y;
    }
}

// ---------------- main persistent recurrence ----------------------------------
#define SM_H    0
#define SM_MX   (UP * HS)                   // 4096
#define SM_MI   (SM_MX + 32 * MXS)          // + 12320
#define SM_X    (SM_MI + 32 * MXS)          // + 12320
#define SM_TOT  (SM_X + NFP * XS)           // + 3744 = 32480 floats = 129920 B

extern __shared__ float smem[];

__global__ __launch_bounds__(RTH, 1) void rec_kernel(
    const float* __restrict__ inp, const float* __restrict__ eps_s,
    float* __restrict__ out)
{
    float* sH  = smem + SM_H;
    float* sMX = smem + SM_MX;
    float* sMI = smem + SM_MI;
    float* sX  = smem + SM_X;

    int b0 = blockIdx.x * RROWS;
    int R = min(RROWS, B - b0);
    int tid = threadIdx.x;
    int grp = (tid >= 192);
    int rb  = grp ? 16 : 0;                // slot base (16-aligned for LDS.128)
    int tg  = tid - (grp ? 192 : 0);       // 0..191
    int j2  = 2 * tg;                      // adjacent column pair

    // pre-packed bias pairs
    float2 bx = *(const float2*)(g_b0p + j2);
    float2 bh = *(const float2*)(g_b1p + j2);
    ull pb0x = pk2(bx.x, bx.x), pb1x = pk2(bx.y, bx.y);
    ull pb0h = pk2(bh.x, bh.x), pb1h = pk2(bh.y, bh.y);

    for (int i = tid; i < UP * HS; i += RTH)  sH[i] = 0.f;
    for (int i = tid; i < NFP * XS; i += RTH) sX[i] = 0.f;

    float xr[8];
    // preload x(t=0)
    {
        int i = 0;
        for (int idx = tid; idx < R * NF; idx += RTH, i++)
            xr[i] = inp[((size_t)(b0 + idx / NF) * T + 0) * NF + (idx % NF)];
    }
    __syncthreads();
    {
        int i = 0;
        for (int idx = tid; idx < R * NF; idx += RTH, i++) {
            int r = idx / NF, f = idx - r * NF;
            int s = r + (r >= 14 ? 2 : 0);
            sX[f * XS + s] = xr[i];
        }
    }
    __syncthreads();

    // ---------- phase 1: 56 warmup GRU steps ----------
    for (int t = 0; t < TS; t++) {
        if (t + 1 < TS) {
            int i = 0;
            for (int idx = tid; idx < R * NF; idx += RTH, i++)
                xr[i] = inp[((size_t)(b0 + idx / NF) * T + (t + 1)) * NF + (idx % NF)];
        }
        gemm_step<NFP, XS>(g_Wkp, pb0x, pb1x, sX, sMX, rb, j2);
        gemm_step<UP,  HS>(g_Up,  pb0h, pb1h, sH, sMI, rb, j2);
        __syncthreads();
        // GRU elementwise
        for (int idx = tid; idx < RROWS * UNITS; idx += RTH) {
            int s28 = idx % RROWS, u = idx / RROWS;
            int s = s28 + (s28 >= 14 ? 2 : 0);
            const float* mx = sMX + s * MXS;
            const float* mi = sMI + s * MXS;
            float z  = sigf(mx[u] + mi[u]);
            float rg = sigf(mx[UNITS + u] + mi[UNITS + u]);
            float hh = tanhfast(fmaf(rg, mi[2 * UNITS + u], mx[2 * UNITS + u]));
            float ho = sH[u * HS + s];
            sH[u * HS + s] = fmaf(z, ho - hh, hh);
        }
        if (t + 1 < TS) {
            int i = 0;
            for (int idx = tid; idx < R * NF; idx += RTH, i++) {
                int r = idx / NF, f = idx - r * NF;
                int s = r + (r >= 14 ? 2 : 0);
                sX[f * XS + s] = xr[i];
            }
        }
        __syncthreads();
    }

    // ---------- phase 2: 28 dense draws + 27 feedback GRU steps ----------
    for (int g = 0; g < GAMMA; g++) {
        if (g < GAMMA - 1) {
            int i = 0;
            for (int idx = tid; idx < R * NF; idx += RTH, i++)
                xr[i] = eps_s[((size_t)g * B + b0 + idx / NF) * NF + (idx % NF)];
        }
        // y = h @ Wf[g] + bf[g] -> sMI
        {
            float2 bf = *(const float2*)(g_Wfb + g * H3P + j2);
            gemm_step<UP, HS>(g_Wf + (size_t)g * UP * H3P,
                              pk2(bf.x, bf.x), pk2(bf.y, bf.y), sH, sMI, rb, j2);
        }
        __syncthreads();
        // dist params -> output + feedback x
        {
            int i = 0;
            for (int idx = tid; idx < R * NF; idx += RTH, i++) {
                int r = idx / NF, f = idx - r * NF;
                int s = r + (r >= 14 ? 2 : 0);
                float loc = sMI[s * MXS + f];
                float sc  = 1e-5f + 0.05f * splus(CC + sMI[s * MXS + NF + f]);
                size_t ob = ((size_t)(b0 + r) * GAMMA + g) * OUT;
                out[ob + f]      = loc;
                out[ob + NF + f] = sc;
                if (g < GAMMA - 1) sX[f * XS + s] = fmaf(sc, xr[i], loc);
            }
        }
        __syncthreads();
        if (g == GAMMA - 1) break;

        gemm_step<NFP, XS>(g_Wkp, pb0x, pb1x, sX, sMX, rb, j2);
        gemm_step<UP,  HS>(g_Up,  pb0h, pb1h, sH, sMI, rb, j2);
        __syncthreads();
        for (int idx = tid; idx < RROWS * UNITS; idx += RTH) {
            int s28 = idx % RROWS, u = idx / RROWS;
            int s = s28 + (s28 >= 14 ? 2 : 0);
            const float* mx = sMX + s * MXS;
            const float* mi = sMI + s * MXS;
            float z  = sigf(mx[u] + mi[u]);
            float rg = sigf(mx[UNITS + u] + mi[UNITS + u]);
            float hh = tanhfast(fmaf(rg, mi[2 * UNITS + u], mx[2 * UNITS + u]));
            float ho = sH[u * HS + s];
            sH[u * HS + s] = fmaf(z, ho - hh, hh);
        }
        __syncthreads();
    }
}

// ---------------- launch ------------------------------------------------------
extern "C" void kernel_launch(void* const* d_in, const int* in_sizes, int n_in,
                              void* d_out, int out_size) {
    const float* inputs = (const float*)d_in[0];
    const float* W_k    = (const float*)d_in[1];
    const float* U      = (const float*)d_in[2];
    const float* b      = (const float*)d_in[3];
    const float* dv_loc = (const float*)d_in[4];
    const float* dv_rho = (const float*)d_in[5];
    const float* eps_w0 = (const float*)d_in[6];
    const float* eps_w  = (const float*)d_in[7];
    const float* eps_s  = (const float*)d_in[8];
    float* out = (float*)d_out;

    prep_kernel<<<(P6 + 255) / 256, 256>>>(W_k, U, b, dv_loc, dv_rho, eps_w0, eps_w);

    cudaFuncSetAttribute(rec_kernel, cudaFuncAttributeMaxDynamicSharedMemorySize,
                         SM_TOT * (int)sizeof(float));
    rec_kernel<<<(B + RROWS - 1) / RROWS, RTH, SM_TOT * sizeof(float)>>>(
        inputs, eps_s, out);
}